// round 9
// baseline (speedup 1.0000x reference)
#include <cuda_runtime.h>

#define HH 128
#define WW 128
#define HW 16384
#define NB 2

// padded plane geometry for cp.async conv loads
#define PADH 130          // rows: gy in [-1, 129)
#define PADW 136          // cols: gx in [-4, 132)
#define PADHW (PADH * PADW)

typedef unsigned long long ull;

// ---------------- f32x2 helpers ----------------------------------------------
__device__ __forceinline__ ull pk2(float lo, float hi) {
    ull r; asm("mov.b64 %0,{%1,%2};" : "=l"(r) : "f"(lo), "f"(hi)); return r;
}
__device__ __forceinline__ void upk2(ull v, float& lo, float& hi) {
    asm("mov.b64 {%0,%1},%2;" : "=f"(lo), "=f"(hi) : "l"(v));
}
__device__ __forceinline__ ull ffma2(ull a, ull b, ull c) {
    ull d; asm("fma.rn.f32x2 %0,%1,%2,%3;" : "=l"(d) : "l"(a), "l"(b), "l"(c));
    return d;
}
__device__ __forceinline__ unsigned smem_u32(const void* p) {
    unsigned a;
    asm("{ .reg .u64 t; cvta.to.shared.u64 t, %1; cvt.u32.u64 %0, t; }"
        : "=r"(a) : "l"(p));
    return a;
}
__device__ __forceinline__ void cp16(unsigned dst, const void* src) {
    asm volatile("cp.async.ca.shared.global [%0],[%1],16;"
                 :: "r"(dst), "l"(src));
}
#define CP_COMMIT() asm volatile("cp.async.commit_group;")
#define CP_WAIT0()  asm volatile("cp.async.wait_group 0;")
#define CP_WAIT1()  asm volatile("cp.async.wait_group 1;")

// ---------------- scratch ----------------------------------------------------
__device__ __align__(16) float g_xlow_pad[NB * 128 * PADHW];
__device__ __align__(16) float g_xup_pad [NB * 256 * PADHW];
__device__ float g_xmerge[NB * HW * 256];         // concat features, NHWC
__device__ float g_offset[NB * 18 * HW];
__device__ float g_mask[NB * 9 * HW];
__device__ __align__(16) ull g_wtp[64 * 36 * 64];    // deform w PAIRS [q][ck][cop]
__device__ __align__(16) ull g_wplow [8 * 32 * 288]; // conv-low  co-pair packs
__device__ __align__(16) ull g_wphigh[8 * 64 * 288]; // conv-high co-pair packs

// ---------------- 1) merged prep kernel --------------------------------------
// blockIdx ranges:
//   [0, NPAD)                 pad x_low           (NB*128*PADHW / 256)
//   [NPAD, NPAD+NUP)          upsample+pad x_high (NB*256*PADHW / 256)
//   [.., +NWT)                deform weight pairs (64*36*64 / 256 = 576)
//   [.., +NWPL)               conv-low  packs     (8*32*288/256 = 288)
//   [.., +NWPH)               conv-high packs     (8*64*288/256 = 576)
#define NPAD  (NB * 128 * PADHW / 256)
#define NUP   (NB * 256 * PADHW / 256)
#define NWT   576
#define NWPL  288
#define NWPH  576
#define NPREP (NPAD + NUP + NWT + NWPL + NWPH)
__global__ void prep_kernel(const float* __restrict__ x_low,
                            const float* __restrict__ x_high,
                            const float* __restrict__ w_low,
                            const float* __restrict__ w_high,
                            const float* __restrict__ wconv) {
    int blk = blockIdx.x;
    if (blk < NPAD) {
        int idx = blk * 256 + threadIdx.x;
        int cp = idx % PADW;
        int rp = (idx / PADW) % PADH;
        int bc = idx / PADHW;
        int gx = cp - 4, gy = rp - 1;
        float v = 0.f;
        if (gx >= 0 && gx < WW && gy >= 0 && gy < HH)
            v = x_low[(size_t)bc * HW + gy * WW + gx];
        g_xlow_pad[idx] = v;
        return;
    }
    blk -= NPAD;
    if (blk < NUP) {
        int idx = blk * 256 + threadIdx.x;
        int cp = idx % PADW;
        int rp = (idx / PADW) % PADH;
        int bc = idx / PADHW;
        int gx = cp - 4, gy = rp - 1;
        float v = 0.f;
        if (gx >= 0 && gx < WW && gy >= 0 && gy < HH) {
            float sy = (gy + 0.5f) * 0.5f - 0.5f;
            float sx = (gx + 0.5f) * 0.5f - 0.5f;
            float y0f = floorf(sy), x0f = floorf(sx);
            float fy = sy - y0f, fx = sx - x0f;
            int y0 = (int)y0f, x0 = (int)x0f;
            int y0c = max(y0, 0), y1c = min(y0 + 1, 63);
            int x0c = max(x0, 0), x1c = min(x0 + 1, 63);
            const float* p = x_high + (size_t)bc * 4096;
            float v00 = p[y0c * 64 + x0c], v01 = p[y0c * 64 + x1c];
            float v10 = p[y1c * 64 + x0c], v11 = p[y1c * 64 + x1c];
            v = (1.f - fy) * ((1.f - fx) * v00 + fx * v01)
              + fy * ((1.f - fx) * v10 + fx * v11);
        }
        g_xup_pad[idx] = v;
        return;
    }
    blk -= NUP;
    if (blk < NWT) {
        int idx = blk * 256 + threadIdx.x;        // 64*36*64
        int cop = idx & 63;
        int rest = idx >> 6;
        int ck = rest % 36, q = rest / 36;
        float w0 = wconv[(size_t)(2 * cop)     * 2304 + q * 36 + ck];
        float w1 = wconv[(size_t)(2 * cop + 1) * 2304 + q * 36 + ck];
        g_wtp[idx] = pk2(w0, w1);
        return;
    }
    blk -= NWT;
    {
        const float* w; ull* dst; int CIN; int t;
        if (blk < NWPL) { w = w_low;  dst = g_wplow;  CIN = 128; t = blk * 256 + threadIdx.x; }
        else            { w = w_high; dst = g_wphigh; CIN = 256; t = (blk - NWPL) * 256 + threadIdx.x; }
        int e = t % 288;
        int rest = t / 288;
        int NCH = CIN / 4;
        int chunk = rest % NCH, cg = rest / NCH;
        int cc = e / 72, rem = e % 72;
        int k = rem >> 3, j = rem & 7;
        int ci = chunk * 4 + cc;
        float w0 = w[((size_t)(cg * 16 + j) * CIN + ci) * 9 + k];
        float w1 = w[((size_t)(cg * 16 + j + 8) * CIN + ci) * 9 + k];
        dst[t] = pk2(w0, w1);
    }
}

// ---------------- 2) fused conv3x3 + BN + ReLU -> g_xmerge NHWC --------------
// (unchanged from round 8 — proven)
#define PATCH_F   (4 * 34 * 40)
#define PATCH_B   (PATCH_F * 4)
#define WBUF_B    (288 * 8)
#define CONV_SMEM_BYTES (3 * (PATCH_B + WBUF_B))   // 72192
__global__ void __launch_bounds__(256, 2) conv_fused(
    const float* __restrict__ g_lo, const float* __restrict__ bb_lo,
    const float* __restrict__ mm_lo, const float* __restrict__ vv_lo,
    const float* __restrict__ g_hi, const float* __restrict__ bb_hi,
    const float* __restrict__ mm_hi, const float* __restrict__ vv_hi)
{
    extern __shared__ __align__(16) char dynsm[];
    float* patchS = (float*)dynsm;
    ull*   wS     = (ull*)(dynsm + 3 * PATCH_B);

    int bz = blockIdx.z;
    bool hi = bz >= 16;
    int bzl = hi ? bz - 16 : bz;
    int b   = bzl >> 3;
    int cg  = bzl & 7;
    int co0 = cg << 4;
    int x0 = blockIdx.x << 5, y0 = blockIdx.y << 5;
    int tx = threadIdx.x, ty = threadIdx.y;
    int tid = ty * 16 + tx;

    const int NCH = hi ? 64 : 32;
    const float* xp = hi ? g_xup_pad + (size_t)b * 256 * PADHW
                         : g_xlow_pad + (size_t)b * 128 * PADHW;
    const ull* wsrc = (hi ? g_wphigh : g_wplow) + (size_t)cg * NCH * 288;
    const float* gg  = hi ? g_hi  : g_lo;
    const float* bbp = hi ? bb_hi : bb_lo;
    const float* mmp = hi ? mm_hi : mm_lo;
    const float* vvp = hi ? vv_hi : vv_lo;
    int chan_base = hi ? 128 : 0;

    unsigned pS0 = smem_u32(patchS);
    unsigned wS0 = smem_u32(wS);

    auto issue = [&](int c, int buf) {
        const float* src_base = xp + (size_t)(c * 4) * PADHW;
        unsigned pdst = pS0 + buf * PATCH_B;
        for (int i = tid; i < 1360; i += 256) {
            int cc = i / 340;
            int r  = i - cc * 340;
            int row = r / 10, seg = r - row * 10;
            const float* src = src_base + (size_t)cc * PADHW
                             + (y0 + row) * PADW + x0 + seg * 4;
            cp16(pdst + (cc * 1360 + row * 40 + seg * 4) * 4, src);
        }
        if (tid < 144)
            cp16(wS0 + buf * WBUF_B + tid * 16, wsrc + (size_t)c * 288 + tid * 2);
        CP_COMMIT();
    };

    ull acc2[32];
#pragma unroll
    for (int i = 0; i < 32; i++) acc2[i] = 0ull;

    issue(0, 0);
    issue(1, 1);

    for (int c = 0; c < NCH; c++) {
        if (c + 1 < NCH) { CP_WAIT1(); } else { CP_WAIT0(); }
        __syncthreads();
        if (c + 2 < NCH) issue(c + 2, (c + 2) % 3);

        int buf = c % 3;
        const float* pd = patchS + buf * PATCH_F;
        const ull*   wp = wS + buf * 288;
#pragma unroll
        for (int cc = 0; cc < 4; cc++) {
            const float* pdc = pd + cc * 1360;
#pragma unroll
            for (int k = 0; k < 9; k++) {
                int dy = k / 3, dx = k % 3;
                float a0 = pdc[(ty + dy) * 40 + tx + dx + 3];
                float a1 = pdc[(ty + dy) * 40 + tx + 16 + dx + 3];
                float a2 = pdc[(ty + 16 + dy) * 40 + tx + dx + 3];
                float a3 = pdc[(ty + 16 + dy) * 40 + tx + 16 + dx + 3];
                ull p0 = pk2(a0, a0), p1 = pk2(a1, a1);
                ull p2 = pk2(a2, a2), p3 = pk2(a3, a3);
                const ull* wr = wp + (cc * 9 + k) * 8;
#pragma unroll
                for (int j = 0; j < 8; j++) {
                    ull wv = wr[j];
                    acc2[j * 4 + 0] = ffma2(wv, p0, acc2[j * 4 + 0]);
                    acc2[j * 4 + 1] = ffma2(wv, p1, acc2[j * 4 + 1]);
                    acc2[j * 4 + 2] = ffma2(wv, p2, acc2[j * 4 + 2]);
                    acc2[j * 4 + 3] = ffma2(wv, p3, acc2[j * 4 + 3]);
                }
            }
        }
        __syncthreads();
    }

    float sc[16], tc[16];
#pragma unroll
    for (int co = 0; co < 16; co++) {
        int c = co0 + co;
        sc[co] = gg[c] * rsqrtf(vvp[c] + 1e-5f);
        tc[co] = bbp[c] - mmp[c] * sc[co];
    }
#pragma unroll
    for (int q = 0; q < 4; q++) {
        int py = y0 + ty + ((q & 2) << 3);
        int px = x0 + tx + ((q & 1) << 4);
        float* dst = g_xmerge + ((size_t)b * HW + py * WW + px) * 256
                   + chan_base + co0;
        float v[16];
#pragma unroll
        for (int j = 0; j < 8; j++) {
            float lo, hi2;
            int qq = ((q & 2) ? 2 : 0) + (q & 1);
            upk2(acc2[j * 4 + qq], lo, hi2);
            v[j]     = fmaxf(lo  * sc[j]     + tc[j],     0.f);
            v[j + 8] = fmaxf(hi2 * sc[j + 8] + tc[j + 8], 0.f);
        }
#pragma unroll
        for (int c4 = 0; c4 < 4; c4++)
            ((float4*)dst)[c4] =
                make_float4(v[c4*4], v[c4*4+1], v[c4*4+2], v[c4*4+3]);
    }
}

// ---------------- 3) 1x1 convs: offset (18) + mask (9, sigmoid) --------------
__global__ void __launch_bounds__(256) offmask_kernel(
    const float* __restrict__ w_off, const float* __restrict__ b_off,
    const float* __restrict__ w_mask, const float* __restrict__ b_mask)
{
    __shared__ ull wpk[128 * 27];
    int tid = threadIdx.x;
    for (int i = tid; i < 128 * 27; i += 256) {
        int j = i / 27, o = i % 27;
        int c = 2 * j;
        float lo = (o < 18) ? w_off[o * 256 + c]     : w_mask[(o - 18) * 256 + c];
        float hi = (o < 18) ? w_off[o * 256 + c + 1] : w_mask[(o - 18) * 256 + c + 1];
        wpk[i] = pk2(lo, hi);
    }
    __syncthreads();

    int gpix = blockIdx.x * 256 + tid;
    int b = gpix >> 14, pix = gpix & 16383;
    const ull* xp = (const ull*)(g_xmerge + (size_t)gpix * 256);

    ull acc2[27];
#pragma unroll
    for (int o = 0; o < 27; o++) acc2[o] = 0ull;

#pragma unroll 8
    for (int j = 0; j < 128; j++) {
        ull xv = __ldg(xp + j);
#pragma unroll
        for (int o = 0; o < 27; o++)
            acc2[o] = ffma2(wpk[j * 27 + o], xv, acc2[o]);
    }

#pragma unroll
    for (int o = 0; o < 18; o++) {
        float lo, hi; upk2(acc2[o], lo, hi);
        g_offset[((size_t)b * 18 + o) * HW + pix] = lo + hi + b_off[o];
    }
#pragma unroll
    for (int o = 0; o < 9; o++) {
        float lo, hi; upk2(acc2[18 + o], lo, hi);
        float a = lo + hi + b_mask[o];
        g_mask[((size_t)b * 9 + o) * HW + pix] = 1.f / (1.f + __expf(-a));
    }
}

// ---------------- 4) deformable conv 3x3 + ReLU (v2: co-pair lanes) ----------
// block: 8x8 px tile x ALL 128 co; thread = 4 px x 8 co (4 co-pairs).
// GEMM per ck: 4x LDS.128 (2 dup'd-val pairs + 2 weight-pair pairs) + 16 ffma2.
// Dynamic smem (55296 B):
//   [0,     18432)  ull  wsk [36][64]   weight pairs [ck][cop]
//   [18432, 36864)  ull  vals[36][64]   dup'd gathered vals [ck][p]
//   [36864, 46080)  int  mI[4][576]
//   [46080, 55296)  float mW[4][576]
#define DEF_SMEM_BYTES 55296
__global__ void __launch_bounds__(256) deform_kernel(float* __restrict__ out)
{
    extern __shared__ __align__(16) char dyn[];
    ull*   wsk  = (ull*)dyn;
    ull*   vals = (ull*)(dyn + 18432);
    int*   mI0  = (int*)(dyn + 36864);
    int*   mI1  = mI0 + 576;
    int*   mI2  = mI1 + 576;
    int*   mI3  = mI2 + 576;
    float* mW0  = (float*)(dyn + 46080);
    float* mW1  = mW0 + 576;
    float* mW2  = mW1 + 576;
    float* mW3  = mW2 + 576;

    int b = blockIdx.z;
    int gx0 = blockIdx.x << 3, gy0 = blockIdx.y << 3;
    int tid = threadIdx.x;
    unsigned wskA = smem_u32(wsk);

    for (int e = tid; e < 576; e += 256) {
        int p = e & 63, k = e >> 6;
        int gy = gy0 + (p >> 3), gx = gx0 + (p & 7);
        int pix = gy * WW + gx;
        float dy = g_offset[((size_t)b * 18 + 2 * k) * HW + pix];
        float dx = g_offset[((size_t)b * 18 + 2 * k + 1) * HW + pix];
        float mk = g_mask[((size_t)b * 9 + k) * HW + pix];
        float ys = (float)gy + (float)(k / 3 - 1) + dy;
        float xs = (float)gx + (float)(k % 3 - 1) + dx;
        float y0f = floorf(ys), x0f = floorf(xs);
        int y0 = (int)y0f, x0 = (int)x0f;
        float wy = ys - y0f, wx = xs - x0f;
        bool vy0 = (y0 >= 0) && (y0 < HH);
        bool vy1 = (y0 + 1 >= 0) && (y0 + 1 < HH);
        bool vx0 = (x0 >= 0) && (x0 < WW);
        bool vx1 = (x0 + 1 >= 0) && (x0 + 1 < WW);
        int y0c = min(max(y0, 0), HH - 1), y1c = min(max(y0 + 1, 0), HH - 1);
        int x0c = min(max(x0, 0), WW - 1), x1c = min(max(x0 + 1, 0), WW - 1);
        mI0[e] = (y0c * WW + x0c) * 256;  mW0[e] = (vy0 && vx0) ? (1.f - wy) * (1.f - wx) * mk : 0.f;
        mI1[e] = (y0c * WW + x1c) * 256;  mW1[e] = (vy0 && vx1) ? (1.f - wy) * wx * mk : 0.f;
        mI2[e] = (y1c * WW + x0c) * 256;  mW2[e] = (vy1 && vx0) ? wy * (1.f - wx) * mk : 0.f;
        mI3[e] = (y1c * WW + x1c) * 256;  mW3[e] = (vy1 && vx1) ? wy * wx * mk : 0.f;
    }

    ull acc2[16];                 // [r (4 px)][j (4 co-pairs)]
#pragma unroll
    for (int i = 0; i < 16; i++) acc2[i] = 0ull;

    const float* xb = g_xmerge + (size_t)b * HW * 256;
    int ppg = tid & 15;      // pixels ppg*4 .. ppg*4+3
    int cog = tid >> 4;      // co-pairs cog*4 .. cog*4+3 (cos cog*8..cog*8+7)

    for (int q = 0; q < 64; q++) {
        int c0 = q * 4;
        __syncthreads();     // previous GEMM done reading vals/wsk
        // gather: 4 channels per corner via float4; store dup'd ull
        for (int e = tid; e < 576; e += 256) {
            int i0 = mI0[e], i1 = mI1[e], i2 = mI2[e], i3 = mI3[e];
            float w0 = mW0[e], w1 = mW1[e], w2 = mW2[e], w3 = mW3[e];
            float4 v0 = __ldg((const float4*)(xb + i0 + c0));
            float4 v1 = __ldg((const float4*)(xb + i1 + c0));
            float4 v2 = __ldg((const float4*)(xb + i2 + c0));
            float4 v3 = __ldg((const float4*)(xb + i3 + c0));
            int base = (e >> 6) * 64 + (e & 63);   // k*64 + p
            float t0 = w0*v0.x + w1*v1.x + w2*v2.x + w3*v3.x;
            float t1 = w0*v0.y + w1*v1.y + w2*v2.y + w3*v3.y;
            float t2 = w0*v0.z + w1*v1.z + w2*v2.z + w3*v3.z;
            float t3 = w0*v0.w + w1*v1.w + w2*v2.w + w3*v3.w;
            vals[base]        = pk2(t0, t0);
            vals[base + 576]  = pk2(t1, t1);
            vals[base + 1152] = pk2(t2, t2);
            vals[base + 1728] = pk2(t3, t3);
        }
        // weight pairs for this chunk: 1152 float4 via cp.async
        {
            const float4* src = (const float4*)(g_wtp + (size_t)q * 2304);
            for (int i = tid; i < 1152; i += 256)
                cp16(wskA + i * 16, src + i);
            CP_COMMIT();
            CP_WAIT0();
        }
        __syncthreads();
        // GEMM: acc[r][j] += wpair[cog*4+j] * val_dup[ppg*4+r]
#pragma unroll 6
        for (int ck = 0; ck < 36; ck++) {
            ulonglong2 va = *(const ulonglong2*)&vals[ck * 64 + ppg * 4];
            ulonglong2 vb = *(const ulonglong2*)&vals[ck * 64 + ppg * 4 + 2];
            ulonglong2 wa = *(const ulonglong2*)&wsk[ck * 64 + cog * 4];
            ulonglong2 wb = *(const ulonglong2*)&wsk[ck * 64 + cog * 4 + 2];
            acc2[0]  = ffma2(wa.x, va.x, acc2[0]);
            acc2[1]  = ffma2(wa.y, va.x, acc2[1]);
            acc2[2]  = ffma2(wb.x, va.x, acc2[2]);
            acc2[3]  = ffma2(wb.y, va.x, acc2[3]);
            acc2[4]  = ffma2(wa.x, va.y, acc2[4]);
            acc2[5]  = ffma2(wa.y, va.y, acc2[5]);
            acc2[6]  = ffma2(wb.x, va.y, acc2[6]);
            acc2[7]  = ffma2(wb.y, va.y, acc2[7]);
            acc2[8]  = ffma2(wa.x, vb.x, acc2[8]);
            acc2[9]  = ffma2(wa.y, vb.x, acc2[9]);
            acc2[10] = ffma2(wb.x, vb.x, acc2[10]);
            acc2[11] = ffma2(wb.y, vb.x, acc2[11]);
            acc2[12] = ffma2(wa.x, vb.y, acc2[12]);
            acc2[13] = ffma2(wa.y, vb.y, acc2[13]);
            acc2[14] = ffma2(wb.x, vb.y, acc2[14]);
            acc2[15] = ffma2(wb.y, vb.y, acc2[15]);
        }
    }

    // epilogue: ReLU + NCHW store (acc lanes = (co, co+1) for one pixel)
#pragma unroll
    for (int r = 0; r < 4; r++) {
        int p = ppg * 4 + r;
        int gy = gy0 + (p >> 3), gx = gx0 + (p & 7);
        int pix = gy * WW + gx;
#pragma unroll
        for (int j = 0; j < 4; j++) {
            float a0, a1; upk2(acc2[r * 4 + j], a0, a1);
            int co = cog * 8 + 2 * j;
            out[((size_t)b * 128 + co) * HW + pix]     = fmaxf(a0, 0.f);
            out[((size_t)b * 128 + co + 1) * HW + pix] = fmaxf(a1, 0.f);
        }
    }
}

// ---------------- launch -----------------------------------------------------
extern "C" void kernel_launch(void* const* d_in, const int* in_sizes, int n_in,
                              void* d_out, int out_size) {
    const float* x_low  = (const float*)d_in[0];
    const float* x_high = (const float*)d_in[1];
    const float* w_low  = (const float*)d_in[2];
    const float* g_low  = (const float*)d_in[3];
    const float* b_low  = (const float*)d_in[4];
    const float* m_low  = (const float*)d_in[5];
    const float* v_low  = (const float*)d_in[6];
    const float* w_high = (const float*)d_in[7];
    const float* g_high = (const float*)d_in[8];
    const float* b_high = (const float*)d_in[9];
    const float* m_high = (const float*)d_in[10];
    const float* v_high = (const float*)d_in[11];
    const float* w_off  = (const float*)d_in[12];
    const float* b_off  = (const float*)d_in[13];
    const float* w_mask = (const float*)d_in[14];
    const float* b_mask = (const float*)d_in[15];
    const float* w_conv = (const float*)d_in[16];
    float* out = (float*)d_out;

    cudaFuncSetAttribute(deform_kernel,
                         cudaFuncAttributeMaxDynamicSharedMemorySize,
                         DEF_SMEM_BYTES);
    cudaFuncSetAttribute(conv_fused,
                         cudaFuncAttributeMaxDynamicSharedMemorySize,
                         CONV_SMEM_BYTES);

    prep_kernel<<<NPREP, 256>>>(x_low, x_high, w_low, w_high, w_conv);

    conv_fused<<<dim3(4, 4, 32), dim3(16, 16), CONV_SMEM_BYTES>>>(
        g_low, b_low, m_low, v_low, g_high, b_high, m_high, v_high);

    offmask_kernel<<<128, 256>>>(w_off, b_off, w_mask, b_mask);

    deform_kernel<<<dim3(16, 16, NB), 256, DEF_SMEM_BYTES>>>(out);
}

// round 11
// speedup vs baseline: 1.1350x; 1.1350x over previous
#include <cuda_runtime.h>

#define HH 128
#define WW 128
#define HW 16384
#define NB 2

// padded plane geometry for cp.async conv loads
#define PADH 130          // rows: gy in [-1, 129)
#define PADW 136          // cols: gx in [-4, 132)
#define PADHW (PADH * PADW)

typedef unsigned long long ull;

// ---------------- f32x2 helpers ----------------------------------------------
__device__ __forceinline__ ull pk2(float lo, float hi) {
    ull r; asm("mov.b64 %0,{%1,%2};" : "=l"(r) : "f"(lo), "f"(hi)); return r;
}
__device__ __forceinline__ void upk2(ull v, float& lo, float& hi) {
    asm("mov.b64 {%0,%1},%2;" : "=f"(lo), "=f"(hi) : "l"(v));
}
__device__ __forceinline__ ull ffma2(ull a, ull b, ull c) {
    ull d; asm("fma.rn.f32x2 %0,%1,%2,%3;" : "=l"(d) : "l"(a), "l"(b), "l"(c));
    return d;
}
__device__ __forceinline__ unsigned smem_u32(const void* p) {
    unsigned a;
    asm("{ .reg .u64 t; cvta.to.shared.u64 t, %1; cvt.u32.u64 %0, t; }"
        : "=r"(a) : "l"(p));
    return a;
}
__device__ __forceinline__ void cp16(unsigned dst, const void* src) {
    asm volatile("cp.async.ca.shared.global [%0],[%1],16;"
                 :: "r"(dst), "l"(src));
}
#define CP_COMMIT() asm volatile("cp.async.commit_group;")
#define CP_WAIT0()  asm volatile("cp.async.wait_group 0;")
#define CP_WAIT1()  asm volatile("cp.async.wait_group 1;")

// ---------------- scratch ----------------------------------------------------
__device__ __align__(16) float g_xlow_pad[NB * 128 * PADHW];
__device__ __align__(16) float g_xup_pad [NB * 256 * PADHW];
__device__ float g_xmerge[NB * HW * 256];         // concat features, NHWC
__device__ float g_offset[NB * 18 * HW];
__device__ float g_mask[NB * 9 * HW];
__device__ __align__(16) ull g_wtd[64 * 36 * 128];   // deform w dup'd [q][ck][co]
__device__ __align__(16) ull g_wplow [8 * 32 * 288]; // conv-low  co-pair packs
__device__ __align__(16) ull g_wphigh[8 * 64 * 288]; // conv-high co-pair packs

// ---------------- 1) merged prep kernel --------------------------------------
// blockIdx ranges:
//   [0, NPAD)        pad x_low
//   [+NUP)           upsample+pad x_high
//   [+NWT)           deform weights dup'd (64*36*128/256 = 1152)
//   [+NWPL)          conv-low packs  (288)
//   [+NWPH)          conv-high packs (576)
#define NPAD  (NB * 128 * PADHW / 256)
#define NUP   (NB * 256 * PADHW / 256)
#define NWT   1152
#define NWPL  288
#define NWPH  576
#define NPREP (NPAD + NUP + NWT + NWPL + NWPH)
__global__ void prep_kernel(const float* __restrict__ x_low,
                            const float* __restrict__ x_high,
                            const float* __restrict__ w_low,
                            const float* __restrict__ w_high,
                            const float* __restrict__ wconv) {
    int blk = blockIdx.x;
    if (blk < NPAD) {
        int idx = blk * 256 + threadIdx.x;
        int cp = idx % PADW;
        int rp = (idx / PADW) % PADH;
        int bc = idx / PADHW;
        int gx = cp - 4, gy = rp - 1;
        float v = 0.f;
        if (gx >= 0 && gx < WW && gy >= 0 && gy < HH)
            v = x_low[(size_t)bc * HW + gy * WW + gx];
        g_xlow_pad[idx] = v;
        return;
    }
    blk -= NPAD;
    if (blk < NUP) {
        int idx = blk * 256 + threadIdx.x;
        int cp = idx % PADW;
        int rp = (idx / PADW) % PADH;
        int bc = idx / PADHW;
        int gx = cp - 4, gy = rp - 1;
        float v = 0.f;
        if (gx >= 0 && gx < WW && gy >= 0 && gy < HH) {
            float sy = (gy + 0.5f) * 0.5f - 0.5f;
            float sx = (gx + 0.5f) * 0.5f - 0.5f;
            float y0f = floorf(sy), x0f = floorf(sx);
            float fy = sy - y0f, fx = sx - x0f;
            int y0 = (int)y0f, x0 = (int)x0f;
            int y0c = max(y0, 0), y1c = min(y0 + 1, 63);
            int x0c = max(x0, 0), x1c = min(x0 + 1, 63);
            const float* p = x_high + (size_t)bc * 4096;
            float v00 = p[y0c * 64 + x0c], v01 = p[y0c * 64 + x1c];
            float v10 = p[y1c * 64 + x0c], v11 = p[y1c * 64 + x1c];
            v = (1.f - fy) * ((1.f - fx) * v00 + fx * v01)
              + fy * ((1.f - fx) * v10 + fx * v11);
        }
        g_xup_pad[idx] = v;
        return;
    }
    blk -= NUP;
    if (blk < NWT) {
        int idx = blk * 256 + threadIdx.x;        // 64*36*128
        int co = idx & 127;
        int rest = idx >> 7;
        int ck = rest % 36, q = rest / 36;
        float w = wconv[(size_t)co * 2304 + q * 36 + ck];
        g_wtd[idx] = pk2(w, w);
        return;
    }
    blk -= NWT;
    {
        const float* w; ull* dst; int CIN; int t;
        if (blk < NWPL) { w = w_low;  dst = g_wplow;  CIN = 128; t = blk * 256 + threadIdx.x; }
        else            { w = w_high; dst = g_wphigh; CIN = 256; t = (blk - NWPL) * 256 + threadIdx.x; }
        int e = t % 288;
        int rest = t / 288;
        int NCH = CIN / 4;
        int chunk = rest % NCH, cg = rest / NCH;
        int cc = e / 72, rem = e % 72;
        int k = rem >> 3, j = rem & 7;
        int ci = chunk * 4 + cc;
        float w0 = w[((size_t)(cg * 16 + j) * CIN + ci) * 9 + k];
        float w1 = w[((size_t)(cg * 16 + j + 8) * CIN + ci) * 9 + k];
        dst[t] = pk2(w0, w1);
    }
}

// ---------------- 2) fused conv3x3 + BN + ReLU -> g_xmerge NHWC --------------
// (unchanged — proven at 1689)
#define PATCH_F   (4 * 34 * 40)
#define PATCH_B   (PATCH_F * 4)
#define WBUF_B    (288 * 8)
#define CONV_SMEM_BYTES (3 * (PATCH_B + WBUF_B))   // 72192
__global__ void __launch_bounds__(256, 2) conv_fused(
    const float* __restrict__ g_lo, const float* __restrict__ bb_lo,
    const float* __restrict__ mm_lo, const float* __restrict__ vv_lo,
    const float* __restrict__ g_hi, const float* __restrict__ bb_hi,
    const float* __restrict__ mm_hi, const float* __restrict__ vv_hi)
{
    extern __shared__ __align__(16) char dynsm[];
    float* patchS = (float*)dynsm;
    ull*   wS     = (ull*)(dynsm + 3 * PATCH_B);

    int bz = blockIdx.z;
    bool hi = bz >= 16;
    int bzl = hi ? bz - 16 : bz;
    int b   = bzl >> 3;
    int cg  = bzl & 7;
    int co0 = cg << 4;
    int x0 = blockIdx.x << 5, y0 = blockIdx.y << 5;
    int tx = threadIdx.x, ty = threadIdx.y;
    int tid = ty * 16 + tx;

    const int NCH = hi ? 64 : 32;
    const float* xp = hi ? g_xup_pad + (size_t)b * 256 * PADHW
                         : g_xlow_pad + (size_t)b * 128 * PADHW;
    const ull* wsrc = (hi ? g_wphigh : g_wplow) + (size_t)cg * NCH * 288;
    const float* gg  = hi ? g_hi  : g_lo;
    const float* bbp = hi ? bb_hi : bb_lo;
    const float* mmp = hi ? mm_hi : mm_lo;
    const float* vvp = hi ? vv_hi : vv_lo;
    int chan_base = hi ? 128 : 0;

    unsigned pS0 = smem_u32(patchS);
    unsigned wS0 = smem_u32(wS);

    auto issue = [&](int c, int buf) {
        const float* src_base = xp + (size_t)(c * 4) * PADHW;
        unsigned pdst = pS0 + buf * PATCH_B;
        for (int i = tid; i < 1360; i += 256) {
            int cc = i / 340;
            int r  = i - cc * 340;
            int row = r / 10, seg = r - row * 10;
            const float* src = src_base + (size_t)cc * PADHW
                             + (y0 + row) * PADW + x0 + seg * 4;
            cp16(pdst + (cc * 1360 + row * 40 + seg * 4) * 4, src);
        }
        if (tid < 144)
            cp16(wS0 + buf * WBUF_B + tid * 16, wsrc + (size_t)c * 288 + tid * 2);
        CP_COMMIT();
    };

    ull acc2[32];
#pragma unroll
    for (int i = 0; i < 32; i++) acc2[i] = 0ull;

    issue(0, 0);
    issue(1, 1);

    for (int c = 0; c < NCH; c++) {
        if (c + 1 < NCH) { CP_WAIT1(); } else { CP_WAIT0(); }
        __syncthreads();
        if (c + 2 < NCH) issue(c + 2, (c + 2) % 3);

        int buf = c % 3;
        const float* pd = patchS + buf * PATCH_F;
        const ull*   wp = wS + buf * 288;
#pragma unroll
        for (int cc = 0; cc < 4; cc++) {
            const float* pdc = pd + cc * 1360;
#pragma unroll
            for (int k = 0; k < 9; k++) {
                int dy = k / 3, dx = k % 3;
                float a0 = pdc[(ty + dy) * 40 + tx + dx + 3];
                float a1 = pdc[(ty + dy) * 40 + tx + 16 + dx + 3];
                float a2 = pdc[(ty + 16 + dy) * 40 + tx + dx + 3];
                float a3 = pdc[(ty + 16 + dy) * 40 + tx + 16 + dx + 3];
                ull p0 = pk2(a0, a0), p1 = pk2(a1, a1);
                ull p2 = pk2(a2, a2), p3 = pk2(a3, a3);
                const ull* wr = wp + (cc * 9 + k) * 8;
#pragma unroll
                for (int j = 0; j < 8; j++) {
                    ull wv = wr[j];
                    acc2[j * 4 + 0] = ffma2(wv, p0, acc2[j * 4 + 0]);
                    acc2[j * 4 + 1] = ffma2(wv, p1, acc2[j * 4 + 1]);
                    acc2[j * 4 + 2] = ffma2(wv, p2, acc2[j * 4 + 2]);
                    acc2[j * 4 + 3] = ffma2(wv, p3, acc2[j * 4 + 3]);
                }
            }
        }
        __syncthreads();
    }

    float sc[16], tc[16];
#pragma unroll
    for (int co = 0; co < 16; co++) {
        int c = co0 + co;
        sc[co] = gg[c] * rsqrtf(vvp[c] + 1e-5f);
        tc[co] = bbp[c] - mmp[c] * sc[co];
    }
#pragma unroll
    for (int q = 0; q < 4; q++) {
        int py = y0 + ty + ((q & 2) << 3);
        int px = x0 + tx + ((q & 1) << 4);
        float* dst = g_xmerge + ((size_t)b * HW + py * WW + px) * 256
                   + chan_base + co0;
        float v[16];
#pragma unroll
        for (int j = 0; j < 8; j++) {
            float lo, hi2;
            int qq = ((q & 2) ? 2 : 0) + (q & 1);
            upk2(acc2[j * 4 + qq], lo, hi2);
            v[j]     = fmaxf(lo  * sc[j]     + tc[j],     0.f);
            v[j + 8] = fmaxf(hi2 * sc[j + 8] + tc[j + 8], 0.f);
        }
#pragma unroll
        for (int c4 = 0; c4 < 4; c4++)
            ((float4*)dst)[c4] =
                make_float4(v[c4*4], v[c4*4+1], v[c4*4+2], v[c4*4+3]);
    }
}

// ---------------- 3) 1x1 convs: offset (18) + mask (9, sigmoid) --------------
__global__ void __launch_bounds__(256) offmask_kernel(
    const float* __restrict__ w_off, const float* __restrict__ b_off,
    const float* __restrict__ w_mask, const float* __restrict__ b_mask)
{
    __shared__ ull wpk[128 * 27];
    int tid = threadIdx.x;
    for (int i = tid; i < 128 * 27; i += 256) {
        int j = i / 27, o = i % 27;
        int c = 2 * j;
        float lo = (o < 18) ? w_off[o * 256 + c]     : w_mask[(o - 18) * 256 + c];
        float hi = (o < 18) ? w_off[o * 256 + c + 1] : w_mask[(o - 18) * 256 + c + 1];
        wpk[i] = pk2(lo, hi);
    }
    __syncthreads();

    int gpix = blockIdx.x * 256 + tid;
    int b = gpix >> 14, pix = gpix & 16383;
    const ull* xp = (const ull*)(g_xmerge + (size_t)gpix * 256);

    ull acc2[27];
#pragma unroll
    for (int o = 0; o < 27; o++) acc2[o] = 0ull;

#pragma unroll 8
    for (int j = 0; j < 128; j++) {
        ull xv = __ldg(xp + j);
#pragma unroll
        for (int o = 0; o < 27; o++)
            acc2[o] = ffma2(wpk[j * 27 + o], xv, acc2[o]);
    }

#pragma unroll
    for (int o = 0; o < 18; o++) {
        float lo, hi; upk2(acc2[o], lo, hi);
        g_offset[((size_t)b * 18 + o) * HW + pix] = lo + hi + b_off[o];
    }
#pragma unroll
    for (int o = 0; o < 9; o++) {
        float lo, hi; upk2(acc2[18 + o], lo, hi);
        float a = lo + hi + b_mask[o];
        g_mask[((size_t)b * 9 + o) * HW + pix] = 1.f / (1.f + __expf(-a));
    }
}

// ---------------- 4) deformable conv 3x3 + ReLU (v3) -------------------------
// v1 compute (proven at 1689) + double-buffered cp.async weight prefetch:
// weights for chunk q+1 are issued at the start of GEMM q and waited for
// during the (latency-bound) gather of chunk q+1.
// Dynamic smem (101376 B):
//   [0,      73728)  ull   wsk[2][36*128]  dup'd weights, double-buffered
//   [73728,  82944)  float vals[36*64]
//   [82944,  92160)  int   mI[4][576]
//   [92160, 101376)  float mW[4][576]
#define DEF_SMEM_BYTES 101376
__global__ void __launch_bounds__(256) deform_kernel(float* __restrict__ out)
{
    extern __shared__ __align__(16) char dyn[];
    ull*   wskB = (ull*)dyn;                    // [2][4608]
    float* vals = (float*)(dyn + 73728);
    int*   mI0  = (int*)(dyn + 82944);
    int*   mI1  = mI0 + 576;
    int*   mI2  = mI1 + 576;
    int*   mI3  = mI2 + 576;
    float* mW0  = (float*)(dyn + 92160);
    float* mW1  = mW0 + 576;
    float* mW2  = mW1 + 576;
    float* mW3  = mW2 + 576;

    int b = blockIdx.z;
    int gx0 = blockIdx.x << 3, gy0 = blockIdx.y << 3;
    int tid = threadIdx.x;
    unsigned wskA = smem_u32(wskB);

    // issue weight copy for chunk q into buffer buf (9 cp16/thread)
    auto issue_w = [&](int q, int buf) {
        const float4* src = (const float4*)(g_wtd + (size_t)q * 4608);
        unsigned dst = wskA + buf * 36864;
#pragma unroll
        for (int j = 0; j < 9; j++) {
            int i = tid + j * 256;
            cp16(dst + i * 16, src + i);
        }
        CP_COMMIT();
    };

    for (int e = tid; e < 576; e += 256) {
        int p = e & 63, k = e >> 6;
        int gy = gy0 + (p >> 3), gx = gx0 + (p & 7);
        int pix = gy * WW + gx;
        float dy = g_offset[((size_t)b * 18 + 2 * k) * HW + pix];
        float dx = g_offset[((size_t)b * 18 + 2 * k + 1) * HW + pix];
        float mk = g_mask[((size_t)b * 9 + k) * HW + pix];
        float ys = (float)gy + (float)(k / 3 - 1) + dy;
        float xs = (float)gx + (float)(k % 3 - 1) + dx;
        float y0f = floorf(ys), x0f = floorf(xs);
        int y0 = (int)y0f, x0 = (int)x0f;
        float wy = ys - y0f, wx = xs - x0f;
        bool vy0 = (y0 >= 0) && (y0 < HH);
        bool vy1 = (y0 + 1 >= 0) && (y0 + 1 < HH);
        bool vx0 = (x0 >= 0) && (x0 < WW);
        bool vx1 = (x0 + 1 >= 0) && (x0 + 1 < WW);
        int y0c = min(max(y0, 0), HH - 1), y1c = min(max(y0 + 1, 0), HH - 1);
        int x0c = min(max(x0, 0), WW - 1), x1c = min(max(x0 + 1, 0), WW - 1);
        mI0[e] = (y0c * WW + x0c) * 256;  mW0[e] = (vy0 && vx0) ? (1.f - wy) * (1.f - wx) * mk : 0.f;
        mI1[e] = (y0c * WW + x1c) * 256;  mW1[e] = (vy0 && vx1) ? (1.f - wy) * wx * mk : 0.f;
        mI2[e] = (y1c * WW + x0c) * 256;  mW2[e] = (vy1 && vx0) ? wy * (1.f - wx) * mk : 0.f;
        mI3[e] = (y1c * WW + x1c) * 256;  mW3[e] = (vy1 && vx1) ? wy * wx * mk : 0.f;
    }

    // prologue: weights for chunk 0 in flight during meta setup + first gather
    issue_w(0, 0);

    ull acc2[16];                 // [j (8 co)][pr (2 px-pairs)]
#pragma unroll
    for (int i = 0; i < 16; i++) acc2[i] = 0ull;

    const float* xb = g_xmerge + (size_t)b * HW * 256;
    int ppg = tid & 15;      // pixel group: px ppg*4 .. ppg*4+3 (2 pairs)
    int cog = tid >> 4;      // co group:    co cog*8 .. cog*8+7

    for (int q = 0; q < 64; q++) {
        int c0 = q * 4;
        // ---- memory phase: gather chunk q (vals buffer free since sync2) ----
        for (int e = tid; e < 576; e += 256) {
            int i0 = mI0[e], i1 = mI1[e], i2 = mI2[e], i3 = mI3[e];
            float w0 = mW0[e], w1 = mW1[e], w2 = mW2[e], w3 = mW3[e];
            float4 v0 = __ldg((const float4*)(xb + i0 + c0));
            float4 v1 = __ldg((const float4*)(xb + i1 + c0));
            float4 v2 = __ldg((const float4*)(xb + i2 + c0));
            float4 v3 = __ldg((const float4*)(xb + i3 + c0));
            int base = (e >> 6) * 64 + (e & 63);   // k*64 + p
            vals[base]        = w0*v0.x + w1*v1.x + w2*v2.x + w3*v3.x;
            vals[base + 576]  = w0*v0.y + w1*v1.y + w2*v2.y + w3*v3.y;
            vals[base + 1152] = w0*v0.z + w1*v1.z + w2*v2.z + w3*v3.z;
            vals[base + 1728] = w0*v0.w + w1*v1.w + w2*v2.w + w3*v3.w;
        }
        CP_WAIT0();          // weights(q) landed (only group in flight)
        __syncthreads();     // vals + weights visible to all

        // ---- GEMM phase: prefetch weights(q+1) into the other buffer -------
        if (q + 1 < 64) issue_w(q + 1, (q + 1) & 1);

        const ull* wsk = wskB + (q & 1) * 4608;
#pragma unroll 6
        for (int ck = 0; ck < 36; ck++) {
            ull v0 = *(const ull*)&vals[ck * 64 + ppg * 4];
            ull v1 = *(const ull*)&vals[ck * 64 + ppg * 4 + 2];
            const ull* wr = wsk + ck * 128 + cog * 8;
#pragma unroll
            for (int j = 0; j < 8; j++) {
                ull wv = wr[j];
                acc2[j * 2 + 0] = ffma2(wv, v0, acc2[j * 2 + 0]);
                acc2[j * 2 + 1] = ffma2(wv, v1, acc2[j * 2 + 1]);
            }
        }
        __syncthreads();     // GEMM done before vals is re-gathered
    }

    // epilogue: ReLU + NCHW store (float2: pixel pairs are gx-contiguous)
#pragma unroll
    for (int j = 0; j < 8; j++) {
        int co = cog * 8 + j;
#pragma unroll
        for (int pr = 0; pr < 2; pr++) {
            float a0, a1; upk2(acc2[j * 2 + pr], a0, a1);
            int p = ppg * 4 + pr * 2;
            int gy = gy0 + (p >> 3), gx = gx0 + (p & 7);
            *(float2*)&out[((size_t)b * 128 + co) * HW + gy * WW + gx] =
                make_float2(fmaxf(a0, 0.f), fmaxf(a1, 0.f));
        }
    }
}

// ---------------- launch -----------------------------------------------------
extern "C" void kernel_launch(void* const* d_in, const int* in_sizes, int n_in,
                              void* d_out, int out_size) {
    const float* x_low  = (const float*)d_in[0];
    const float* x_high = (const float*)d_in[1];
    const float* w_low  = (const float*)d_in[2];
    const float* g_low  = (const float*)d_in[3];
    const float* b_low  = (const float*)d_in[4];
    const float* m_low  = (const float*)d_in[5];
    const float* v_low  = (const float*)d_in[6];
    const float* w_high = (const float*)d_in[7];
    const float* g_high = (const float*)d_in[8];
    const float* b_high = (const float*)d_in[9];
    const float* m_high = (const float*)d_in[10];
    const float* v_high = (const float*)d_in[11];
    const float* w_off  = (const float*)d_in[12];
    const float* b_off  = (const float*)d_in[13];
    const float* w_mask = (const float*)d_in[14];
    const float* b_mask = (const float*)d_in[15];
    const float* w_conv = (const float*)d_in[16];
    float* out = (float*)d_out;

    cudaFuncSetAttribute(deform_kernel,
                         cudaFuncAttributeMaxDynamicSharedMemorySize,
                         DEF_SMEM_BYTES);
    cudaFuncSetAttribute(conv_fused,
                         cudaFuncAttributeMaxDynamicSharedMemorySize,
                         CONV_SMEM_BYTES);

    prep_kernel<<<NPREP, 256>>>(x_low, x_high, w_low, w_high, w_conv);

    conv_fused<<<dim3(4, 4, 32), dim3(16, 16), CONV_SMEM_BYTES>>>(
        g_low, b_low, m_low, v_low, g_high, b_high, m_high, v_high);

    offmask_kernel<<<128, 256>>>(w_off, b_off, w_mask, b_mask);

    deform_kernel<<<dim3(16, 16, NB), 256, DEF_SMEM_BYTES>>>(out);
}

// round 12
// speedup vs baseline: 1.3944x; 1.2286x over previous
#include <cuda_runtime.h>

#define HH 128
#define WW 128
#define HW 16384
#define NB 2

// padded plane geometry for cp.async conv loads
#define PADH 130
#define PADW 136
#define PADHW (PADH * PADW)

typedef unsigned long long ull;

// ---------------- f32x2 helpers ----------------------------------------------
__device__ __forceinline__ ull pk2(float lo, float hi) {
    ull r; asm("mov.b64 %0,{%1,%2};" : "=l"(r) : "f"(lo), "f"(hi)); return r;
}
__device__ __forceinline__ void upk2(ull v, float& lo, float& hi) {
    asm("mov.b64 {%0,%1},%2;" : "=f"(lo), "=f"(hi) : "l"(v));
}
__device__ __forceinline__ ull ffma2(ull a, ull b, ull c) {
    ull d; asm("fma.rn.f32x2 %0,%1,%2,%3;" : "=l"(d) : "l"(a), "l"(b), "l"(c));
    return d;
}
__device__ __forceinline__ unsigned smem_u32(const void* p) {
    unsigned a;
    asm("{ .reg .u64 t; cvta.to.shared.u64 t, %1; cvt.u32.u64 %0, t; }"
        : "=r"(a) : "l"(p));
    return a;
}
__device__ __forceinline__ void cp16(unsigned dst, const void* src) {
    asm volatile("cp.async.ca.shared.global [%0],[%1],16;"
                 :: "r"(dst), "l"(src));
}
#define CP_COMMIT() asm volatile("cp.async.commit_group;")
#define CP_WAIT0()  asm volatile("cp.async.wait_group 0;")
#define CP_WAIT1()  asm volatile("cp.async.wait_group 1;")

// ---------------- scratch ----------------------------------------------------
__device__ __align__(16) float g_xlow_pad[NB * 128 * PADHW];
__device__ __align__(16) float g_xup_pad [NB * 256 * PADHW];
__device__ float g_xmerge[NB * HW * 256];            // concat features, NHWC
__device__ float g_offset[NB * 18 * HW];
__device__ float g_mask[NB * 9 * HW];
__device__ __align__(16) ull g_wtp[64 * 36 * 64];    // deform w PAIRS [q][ck][cop]
__device__ __align__(16) ull g_wplow [8 * 32 * 288]; // conv-low  co-pair packs
__device__ __align__(16) ull g_wphigh[8 * 64 * 288]; // conv-high co-pair packs

// ---------------- 1) merged prep kernel --------------------------------------
#define NPAD  (NB * 128 * PADHW / 256)
#define NUP   (NB * 256 * PADHW / 256)
#define NWT   576
#define NWPL  288
#define NWPH  576
#define NPREP (NPAD + NUP + NWT + NWPL + NWPH)
__global__ void prep_kernel(const float* __restrict__ x_low,
                            const float* __restrict__ x_high,
                            const float* __restrict__ w_low,
                            const float* __restrict__ w_high,
                            const float* __restrict__ wconv) {
    int blk = blockIdx.x;
    if (blk < NPAD) {
        int idx = blk * 256 + threadIdx.x;
        int cp = idx % PADW;
        int rp = (idx / PADW) % PADH;
        int bc = idx / PADHW;
        int gx = cp - 4, gy = rp - 1;
        float v = 0.f;
        if (gx >= 0 && gx < WW && gy >= 0 && gy < HH)
            v = x_low[(size_t)bc * HW + gy * WW + gx];
        g_xlow_pad[idx] = v;
        return;
    }
    blk -= NPAD;
    if (blk < NUP) {
        int idx = blk * 256 + threadIdx.x;
        int cp = idx % PADW;
        int rp = (idx / PADW) % PADH;
        int bc = idx / PADHW;
        int gx = cp - 4, gy = rp - 1;
        float v = 0.f;
        if (gx >= 0 && gx < WW && gy >= 0 && gy < HH) {
            float sy = (gy + 0.5f) * 0.5f - 0.5f;
            float sx = (gx + 0.5f) * 0.5f - 0.5f;
            float y0f = floorf(sy), x0f = floorf(sx);
            float fy = sy - y0f, fx = sx - x0f;
            int y0 = (int)y0f, x0 = (int)x0f;
            int y0c = max(y0, 0), y1c = min(y0 + 1, 63);
            int x0c = max(x0, 0), x1c = min(x0 + 1, 63);
            const float* p = x_high + (size_t)bc * 4096;
            float v00 = p[y0c * 64 + x0c], v01 = p[y0c * 64 + x1c];
            float v10 = p[y1c * 64 + x0c], v11 = p[y1c * 64 + x1c];
            v = (1.f - fy) * ((1.f - fx) * v00 + fx * v01)
              + fy * ((1.f - fx) * v10 + fx * v11);
        }
        g_xup_pad[idx] = v;
        return;
    }
    blk -= NUP;
    if (blk < NWT) {
        int idx = blk * 256 + threadIdx.x;        // 64*36*64
        int cop = idx & 63;
        int rest = idx >> 6;
        int ck = rest % 36, q = rest / 36;
        float w0 = wconv[(size_t)(2 * cop)     * 2304 + q * 36 + ck];
        float w1 = wconv[(size_t)(2 * cop + 1) * 2304 + q * 36 + ck];
        g_wtp[idx] = pk2(w0, w1);
        return;
    }
    blk -= NWT;
    {
        const float* w; ull* dst; int CIN; int t;
        if (blk < NWPL) { w = w_low;  dst = g_wplow;  CIN = 128; t = blk * 256 + threadIdx.x; }
        else            { w = w_high; dst = g_wphigh; CIN = 256; t = (blk - NWPL) * 256 + threadIdx.x; }
        int e = t % 288;
        int rest = t / 288;
        int NCH = CIN / 4;
        int chunk = rest % NCH, cg = rest / NCH;
        int cc = e / 72, rem = e % 72;
        int k = rem >> 3, j = rem & 7;
        int ci = chunk * 4 + cc;
        float w0 = w[((size_t)(cg * 16 + j) * CIN + ci) * 9 + k];
        float w1 = w[((size_t)(cg * 16 + j + 8) * CIN + ci) * 9 + k];
        dst[t] = pk2(w0, w1);
    }
}

// ---------------- 2) fused conv3x3 + BN + ReLU (unchanged, proven) -----------
#define PATCH_F   (4 * 34 * 40)
#define PATCH_B   (PATCH_F * 4)
#define WBUF_B    (288 * 8)
#define CONV_SMEM_BYTES (3 * (PATCH_B + WBUF_B))   // 72192
__global__ void __launch_bounds__(256, 2) conv_fused(
    const float* __restrict__ g_lo, const float* __restrict__ bb_lo,
    const float* __restrict__ mm_lo, const float* __restrict__ vv_lo,
    const float* __restrict__ g_hi, const float* __restrict__ bb_hi,
    const float* __restrict__ mm_hi, const float* __restrict__ vv_hi)
{
    extern __shared__ __align__(16) char dynsm[];
    float* patchS = (float*)dynsm;
    ull*   wS     = (ull*)(dynsm + 3 * PATCH_B);

    int bz = blockIdx.z;
    bool hi = bz >= 16;
    int bzl = hi ? bz - 16 : bz;
    int b   = bzl >> 3;
    int cg  = bzl & 7;
    int co0 = cg << 4;
    int x0 = blockIdx.x << 5, y0 = blockIdx.y << 5;
    int tx = threadIdx.x, ty = threadIdx.y;
    int tid = ty * 16 + tx;

    const int NCH = hi ? 64 : 32;
    const float* xp = hi ? g_xup_pad + (size_t)b * 256 * PADHW
                         : g_xlow_pad + (size_t)b * 128 * PADHW;
    const ull* wsrc = (hi ? g_wphigh : g_wplow) + (size_t)cg * NCH * 288;
    const float* gg  = hi ? g_hi  : g_lo;
    const float* bbp = hi ? bb_hi : bb_lo;
    const float* mmp = hi ? mm_hi : mm_lo;
    const float* vvp = hi ? vv_hi : vv_lo;
    int chan_base = hi ? 128 : 0;

    unsigned pS0 = smem_u32(patchS);
    unsigned wS0 = smem_u32(wS);

    auto issue = [&](int c, int buf) {
        const float* src_base = xp + (size_t)(c * 4) * PADHW;
        unsigned pdst = pS0 + buf * PATCH_B;
        for (int i = tid; i < 1360; i += 256) {
            int cc = i / 340;
            int r  = i - cc * 340;
            int row = r / 10, seg = r - row * 10;
            const float* src = src_base + (size_t)cc * PADHW
                             + (y0 + row) * PADW + x0 + seg * 4;
            cp16(pdst + (cc * 1360 + row * 40 + seg * 4) * 4, src);
        }
        if (tid < 144)
            cp16(wS0 + buf * WBUF_B + tid * 16, wsrc + (size_t)c * 288 + tid * 2);
        CP_COMMIT();
    };

    ull acc2[32];
#pragma unroll
    for (int i = 0; i < 32; i++) acc2[i] = 0ull;

    issue(0, 0);
    issue(1, 1);

    for (int c = 0; c < NCH; c++) {
        if (c + 1 < NCH) { CP_WAIT1(); } else { CP_WAIT0(); }
        __syncthreads();
        if (c + 2 < NCH) issue(c + 2, (c + 2) % 3);

        int buf = c % 3;
        const float* pd = patchS + buf * PATCH_F;
        const ull*   wp = wS + buf * 288;
#pragma unroll
        for (int cc = 0; cc < 4; cc++) {
            const float* pdc = pd + cc * 1360;
#pragma unroll
            for (int k = 0; k < 9; k++) {
                int dy = k / 3, dx = k % 3;
                float a0 = pdc[(ty + dy) * 40 + tx + dx + 3];
                float a1 = pdc[(ty + dy) * 40 + tx + 16 + dx + 3];
                float a2 = pdc[(ty + 16 + dy) * 40 + tx + dx + 3];
                float a3 = pdc[(ty + 16 + dy) * 40 + tx + 16 + dx + 3];
                ull p0 = pk2(a0, a0), p1 = pk2(a1, a1);
                ull p2 = pk2(a2, a2), p3 = pk2(a3, a3);
                const ull* wr = wp + (cc * 9 + k) * 8;
#pragma unroll
                for (int j = 0; j < 8; j++) {
                    ull wv = wr[j];
                    acc2[j * 4 + 0] = ffma2(wv, p0, acc2[j * 4 + 0]);
                    acc2[j * 4 + 1] = ffma2(wv, p1, acc2[j * 4 + 1]);
                    acc2[j * 4 + 2] = ffma2(wv, p2, acc2[j * 4 + 2]);
                    acc2[j * 4 + 3] = ffma2(wv, p3, acc2[j * 4 + 3]);
                }
            }
        }
        __syncthreads();
    }

    float sc[16], tc[16];
#pragma unroll
    for (int co = 0; co < 16; co++) {
        int c = co0 + co;
        sc[co] = gg[c] * rsqrtf(vvp[c] + 1e-5f);
        tc[co] = bbp[c] - mmp[c] * sc[co];
    }
#pragma unroll
    for (int q = 0; q < 4; q++) {
        int py = y0 + ty + ((q & 2) << 3);
        int px = x0 + tx + ((q & 1) << 4);
        float* dst = g_xmerge + ((size_t)b * HW + py * WW + px) * 256
                   + chan_base + co0;
        float v[16];
#pragma unroll
        for (int j = 0; j < 8; j++) {
            float lo, hi2;
            int qq = ((q & 2) ? 2 : 0) + (q & 1);
            upk2(acc2[j * 4 + qq], lo, hi2);
            v[j]     = fmaxf(lo  * sc[j]     + tc[j],     0.f);
            v[j + 8] = fmaxf(hi2 * sc[j + 8] + tc[j + 8], 0.f);
        }
#pragma unroll
        for (int c4 = 0; c4 < 4; c4++)
            ((float4*)dst)[c4] =
                make_float4(v[c4*4], v[c4*4+1], v[c4*4+2], v[c4*4+3]);
    }
}

// ---------------- 3) 1x1 convs: offset (18) + mask (9, sigmoid) --------------
__global__ void __launch_bounds__(256) offmask_kernel(
    const float* __restrict__ w_off, const float* __restrict__ b_off,
    const float* __restrict__ w_mask, const float* __restrict__ b_mask)
{
    __shared__ ull wpk[128 * 27];
    int tid = threadIdx.x;
    for (int i = tid; i < 128 * 27; i += 256) {
        int j = i / 27, o = i % 27;
        int c = 2 * j;
        float lo = (o < 18) ? w_off[o * 256 + c]     : w_mask[(o - 18) * 256 + c];
        float hi = (o < 18) ? w_off[o * 256 + c + 1] : w_mask[(o - 18) * 256 + c + 1];
        wpk[i] = pk2(lo, hi);
    }
    __syncthreads();

    int gpix = blockIdx.x * 256 + tid;
    int b = gpix >> 14, pix = gpix & 16383;
    const ull* xp = (const ull*)(g_xmerge + (size_t)gpix * 256);

    ull acc2[27];
#pragma unroll
    for (int o = 0; o < 27; o++) acc2[o] = 0ull;

#pragma unroll 8
    for (int j = 0; j < 128; j++) {
        ull xv = __ldg(xp + j);
#pragma unroll
        for (int o = 0; o < 27; o++)
            acc2[o] = ffma2(wpk[j * 27 + o], xv, acc2[o]);
    }

#pragma unroll
    for (int o = 0; o < 18; o++) {
        float lo, hi; upk2(acc2[o], lo, hi);
        g_offset[((size_t)b * 18 + o) * HW + pix] = lo + hi + b_off[o];
    }
#pragma unroll
    for (int o = 0; o < 9; o++) {
        float lo, hi; upk2(acc2[18 + o], lo, hi);
        float a = lo + hi + b_mask[o];
        g_mask[((size_t)b * 9 + o) * HW + pix] = 1.f / (1.f + __expf(-a));
    }
}

// ---------------- 4) deformable conv 3x3 + ReLU (v4) -------------------------
// Channel-parallel gather (16-channel groups; half-warp = 16 consecutive
// channels of one (px,tap) -> coalesced LDG) + co-pair GEMM (non-dup'd
// weight pairs, 6 LDS/ck) + double-buffered cp.async weight prefetch.
// Thread = 4 px x 8 co (4 co-pairs). Dynamic smem (93312 B):
//   [0,     36864)  ull   wskB[2][36*64]   weight pairs, double-buffered
//   [36864, 74880)  float vals[9*16*66]    gathered vals [k][cc][p] pad66
//   [74880, 84096)  int   mI[4][576]
//   [84096, 93312)  float mW[4][576]
#define DEF_SMEM_BYTES 93312
__global__ void __launch_bounds__(256) deform_kernel(float* __restrict__ out)
{
    extern __shared__ __align__(16) char dyn[];
    ull*   wskB = (ull*)dyn;                    // [2][2304]
    float* vals = (float*)(dyn + 36864);        // [ (k*16+cc)*66 + p ]
    int*   mI0  = (int*)(dyn + 74880);
    int*   mI1  = mI0 + 576;
    int*   mI2  = mI1 + 576;
    int*   mI3  = mI2 + 576;
    float* mW0  = (float*)(dyn + 84096);
    float* mW1  = mW0 + 576;
    float* mW2  = mW1 + 576;
    float* mW3  = mW2 + 576;

    int b = blockIdx.z;
    int gx0 = blockIdx.x << 3, gy0 = blockIdx.y << 3;
    int tid = threadIdx.x;
    unsigned wskA = smem_u32(wskB);

    // weight copy for 4-channel chunk q into buffer buf (18432 B = 1152 cp16)
    auto issue_w = [&](int q, int buf) {
        const float4* src = (const float4*)(g_wtp + (size_t)q * 2304);
        unsigned dst = wskA + buf * 18432;
#pragma unroll
        for (int j = 0; j < 5; j++) {
            int i = tid + j * 256;
            if (i < 1152) cp16(dst + i * 16, src + i);
        }
        CP_COMMIT();
    };

    // per-(pixel,tap) meta
    for (int e = tid; e < 576; e += 256) {
        int p = e & 63, k = e >> 6;
        int gy = gy0 + (p >> 3), gx = gx0 + (p & 7);
        int pix = gy * WW + gx;
        float dy = g_offset[((size_t)b * 18 + 2 * k) * HW + pix];
        float dx = g_offset[((size_t)b * 18 + 2 * k + 1) * HW + pix];
        float mk = g_mask[((size_t)b * 9 + k) * HW + pix];
        float ys = (float)gy + (float)(k / 3 - 1) + dy;
        float xs = (float)gx + (float)(k % 3 - 1) + dx;
        float y0f = floorf(ys), x0f = floorf(xs);
        int y0 = (int)y0f, x0 = (int)x0f;
        float wy = ys - y0f, wx = xs - x0f;
        bool vy0 = (y0 >= 0) && (y0 < HH);
        bool vy1 = (y0 + 1 >= 0) && (y0 + 1 < HH);
        bool vx0 = (x0 >= 0) && (x0 < WW);
        bool vx1 = (x0 + 1 >= 0) && (x0 + 1 < WW);
        int y0c = min(max(y0, 0), HH - 1), y1c = min(max(y0 + 1, 0), HH - 1);
        int x0c = min(max(x0, 0), WW - 1), x1c = min(max(x0 + 1, 0), WW - 1);
        mI0[e] = (y0c * WW + x0c) * 256;  mW0[e] = (vy0 && vx0) ? (1.f - wy) * (1.f - wx) * mk : 0.f;
        mI1[e] = (y0c * WW + x1c) * 256;  mW1[e] = (vy0 && vx1) ? (1.f - wy) * wx * mk : 0.f;
        mI2[e] = (y1c * WW + x0c) * 256;  mW2[e] = (vy1 && vx0) ? wy * (1.f - wx) * mk : 0.f;
        mI3[e] = (y1c * WW + x1c) * 256;  mW3[e] = (vy1 && vx1) ? wy * wx * mk : 0.f;
    }

    issue_w(0, 0);        // weights(0) fly under meta + first gather

    ull acc2[16];         // [r (4 px)][j (4 co-pairs)]
#pragma unroll
    for (int i = 0; i < 16; i++) acc2[i] = 0ull;

    const float* xb = g_xmerge + (size_t)b * HW * 256;
    int ppg  = tid & 15;          // pixels ppg*4 .. ppg*4+3
    int cog  = tid >> 4;          // co-pairs cog*4..+3 (cos cog*8..cog*8+7)
    int wid  = tid >> 5;          // gather warp id
    int lane = tid & 31;
    int half = lane >> 4;         // entry selector within pair
    int cch  = lane & 15;         // channel within group

    for (int g = 0; g < 16; g++) {
        __syncthreads();          // vals free (prev group GEMM done) / meta ready
        // ---- gather 16 channels (c0g..c0g+15) for all 576 (px,tap) ---------
        int c0g = g * 16;
        const float* xc = xb + c0g + cch;
        for (int it = 0; it < 36; it++) {
            int e = wid * 72 + it * 2 + half;
            int i0 = mI0[e], i1 = mI1[e], i2 = mI2[e], i3 = mI3[e];
            float w0 = mW0[e], w1 = mW1[e], w2 = mW2[e], w3 = mW3[e];
            float v = w0 * __ldg(xc + i0) + w1 * __ldg(xc + i1)
                    + w2 * __ldg(xc + i2) + w3 * __ldg(xc + i3);
            int k = e >> 6, p = e & 63;
            vals[(k * 16 + cch) * 66 + p] = v;
        }
        // ---- 4 GEMM sub-chunks of 4 channels -------------------------------
        for (int s = 0; s < 4; s++) {
            int q = g * 4 + s;
            CP_WAIT0();           // weights(q) landed
            __syncthreads();      // weights + (s==0) vals visible to all
            if (q + 1 < 64) issue_w(q + 1, (q + 1) & 1);

            const ull* wsk = wskB + (q & 1) * 2304;
            const float* vbase = vals + (s * 4) * 66 + ppg * 4;
#pragma unroll
            for (int cc4 = 0; cc4 < 4; cc4++) {
#pragma unroll
                for (int k = 0; k < 9; k++) {
                    const ull* wr = wsk + (cc4 * 9 + k) * 64 + cog * 4;
                    ull w0 = wr[0], w1 = wr[1], w2 = wr[2], w3 = wr[3];
                    const float* vp = vbase + (k * 16 + cc4) * 66;
                    ull da = pk2(vp[0], vp[0]);
                    ull db = pk2(vp[1], vp[1]);
                    ull dc = pk2(vp[2], vp[2]);
                    ull dd = pk2(vp[3], vp[3]);
                    acc2[0]  = ffma2(w0, da, acc2[0]);
                    acc2[1]  = ffma2(w1, da, acc2[1]);
                    acc2[2]  = ffma2(w2, da, acc2[2]);
                    acc2[3]  = ffma2(w3, da, acc2[3]);
                    acc2[4]  = ffma2(w0, db, acc2[4]);
                    acc2[5]  = ffma2(w1, db, acc2[5]);
                    acc2[6]  = ffma2(w2, db, acc2[6]);
                    acc2[7]  = ffma2(w3, db, acc2[7]);
                    acc2[8]  = ffma2(w0, dc, acc2[8]);
                    acc2[9]  = ffma2(w1, dc, acc2[9]);
                    acc2[10] = ffma2(w2, dc, acc2[10]);
                    acc2[11] = ffma2(w3, dc, acc2[11]);
                    acc2[12] = ffma2(w0, dd, acc2[12]);
                    acc2[13] = ffma2(w1, dd, acc2[13]);
                    acc2[14] = ffma2(w2, dd, acc2[14]);
                    acc2[15] = ffma2(w3, dd, acc2[15]);
                }
            }
            __syncthreads();      // GEMM done before weights buf reuse / vals regather
        }
    }

    // epilogue: ReLU + NCHW store (co pairs per pixel)
#pragma unroll
    for (int r = 0; r < 4; r++) {
        int p = ppg * 4 + r;
        int gy = gy0 + (p >> 3), gx = gx0 + (p & 7);
        int pix = gy * WW + gx;
#pragma unroll
        for (int j = 0; j < 4; j++) {
            float a0, a1; upk2(acc2[r * 4 + j], a0, a1);
            int co = cog * 8 + 2 * j;
            out[((size_t)b * 128 + co) * HW + pix]     = fmaxf(a0, 0.f);
            out[((size_t)b * 128 + co + 1) * HW + pix] = fmaxf(a1, 0.f);
        }
    }
}

// ---------------- launch -----------------------------------------------------
extern "C" void kernel_launch(void* const* d_in, const int* in_sizes, int n_in,
                              void* d_out, int out_size) {
    const float* x_low  = (const float*)d_in[0];
    const float* x_high = (const float*)d_in[1];
    const float* w_low  = (const float*)d_in[2];
    const float* g_low  = (const float*)d_in[3];
    const float* b_low  = (const float*)d_in[4];
    const float* m_low  = (const float*)d_in[5];
    const float* v_low  = (const float*)d_in[6];
    const float* w_high = (const float*)d_in[7];
    const float* g_high = (const float*)d_in[8];
    const float* b_high = (const float*)d_in[9];
    const float* m_high = (const float*)d_in[10];
    const float* v_high = (const float*)d_in[11];
    const float* w_off  = (const float*)d_in[12];
    const float* b_off  = (const float*)d_in[13];
    const float* w_mask = (const float*)d_in[14];
    const float* b_mask = (const float*)d_in[15];
    const float* w_conv = (const float*)d_in[16];
    float* out = (float*)d_out;

    cudaFuncSetAttribute(deform_kernel,
                         cudaFuncAttributeMaxDynamicSharedMemorySize,
                         DEF_SMEM_BYTES);
    cudaFuncSetAttribute(conv_fused,
                         cudaFuncAttributeMaxDynamicSharedMemorySize,
                         CONV_SMEM_BYTES);

    prep_kernel<<<NPREP, 256>>>(x_low, x_high, w_low, w_high, w_conv);

    conv_fused<<<dim3(4, 4, 32), dim3(16, 16), CONV_SMEM_BYTES>>>(
        g_low, b_low, m_low, v_low, g_high, b_high, m_high, v_high);

    offmask_kernel<<<128, 256>>>(w_off, b_off, w_mask, b_mask);

    deform_kernel<<<dim3(16, 16, NB), 256, DEF_SMEM_BYTES>>>(out);
}

// round 15
// speedup vs baseline: 1.4176x; 1.0167x over previous
#include <cuda_runtime.h>

#define HH 128
#define WW 128
#define HW 16384
#define NB 2

// padded plane geometry for cp.async conv loads
#define PADH 130
#define PADW 136
#define PADHW (PADH * PADW)

typedef unsigned long long ull;

// ---------------- f32x2 helpers ----------------------------------------------
__device__ __forceinline__ ull pk2(float lo, float hi) {
    ull r; asm("mov.b64 %0,{%1,%2};" : "=l"(r) : "f"(lo), "f"(hi)); return r;
}
__device__ __forceinline__ void upk2(ull v, float& lo, float& hi) {
    asm("mov.b64 {%0,%1},%2;" : "=f"(lo), "=f"(hi) : "l"(v));
}
__device__ __forceinline__ ull ffma2(ull a, ull b, ull c) {
    ull d; asm("fma.rn.f32x2 %0,%1,%2,%3;" : "=l"(d) : "l"(a), "l"(b), "l"(c));
    return d;
}
__device__ __forceinline__ unsigned smem_u32(const void* p) {
    unsigned a;
    asm("{ .reg .u64 t; cvta.to.shared.u64 t, %1; cvt.u32.u64 %0, t; }"
        : "=r"(a) : "l"(p));
    return a;
}
__device__ __forceinline__ void cp16(unsigned dst, const void* src) {
    asm volatile("cp.async.ca.shared.global [%0],[%1],16;"
                 :: "r"(dst), "l"(src));
}
#define CP_COMMIT() asm volatile("cp.async.commit_group;")
#define CP_WAIT0()  asm volatile("cp.async.wait_group 0;")
#define CP_WAIT1()  asm volatile("cp.async.wait_group 1;")

// ---------------- scratch ----------------------------------------------------
__device__ __align__(16) float g_xlow_pad[NB * 128 * PADHW];
__device__ __align__(16) float g_xup_pad [NB * 256 * PADHW];
__device__ float g_xmerge[NB * HW * 256];            // concat features, NHWC
__device__ float g_offset[NB * 18 * HW];
__device__ float g_mask[NB * 9 * HW];
__device__ __align__(16) ull g_wtp[64 * 36 * 64];    // deform w PAIRS [q][ck][cop]
__device__ __align__(16) ull g_wplow [8 * 32 * 288]; // conv-low  co-pair packs
__device__ __align__(16) ull g_wphigh[8 * 64 * 288]; // conv-high co-pair packs

// ---------------- 1) merged prep kernel --------------------------------------
#define NPAD  (NB * 128 * PADHW / 256)
#define NUP   (NB * 256 * PADHW / 256)
#define NWT   576
#define NWPL  288
#define NWPH  576
#define NPREP (NPAD + NUP + NWT + NWPL + NWPH)
__global__ void prep_kernel(const float* __restrict__ x_low,
                            const float* __restrict__ x_high,
                            const float* __restrict__ w_low,
                            const float* __restrict__ w_high,
                            const float* __restrict__ wconv) {
    int blk = blockIdx.x;
    if (blk < NPAD) {
        int idx = blk * 256 + threadIdx.x;
        int cp = idx % PADW;
        int rp = (idx / PADW) % PADH;
        int bc = idx / PADHW;
        int gx = cp - 4, gy = rp - 1;
        float v = 0.f;
        if (gx >= 0 && gx < WW && gy >= 0 && gy < HH)
            v = x_low[(size_t)bc * HW + gy * WW + gx];
        g_xlow_pad[idx] = v;
        return;
    }
    blk -= NPAD;
    if (blk < NUP) {
        int idx = blk * 256 + threadIdx.x;
        int cp = idx % PADW;
        int rp = (idx / PADW) % PADH;
        int bc = idx / PADHW;
        int gx = cp - 4, gy = rp - 1;
        float v = 0.f;
        if (gx >= 0 && gx < WW && gy >= 0 && gy < HH) {
            float sy = (gy + 0.5f) * 0.5f - 0.5f;
            float sx = (gx + 0.5f) * 0.5f - 0.5f;
            float y0f = floorf(sy), x0f = floorf(sx);
            float fy = sy - y0f, fx = sx - x0f;
            int y0 = (int)y0f, x0 = (int)x0f;
            int y0c = max(y0, 0), y1c = min(y0 + 1, 63);
            int x0c = max(x0, 0), x1c = min(x0 + 1, 63);
            const float* p = x_high + (size_t)bc * 4096;
            float v00 = p[y0c * 64 + x0c], v01 = p[y0c * 64 + x1c];
            float v10 = p[y1c * 64 + x0c], v11 = p[y1c * 64 + x1c];
            v = (1.f - fy) * ((1.f - fx) * v00 + fx * v01)
              + fy * ((1.f - fx) * v10 + fx * v11);
        }
        g_xup_pad[idx] = v;
        return;
    }
    blk -= NUP;
    if (blk < NWT) {
        int idx = blk * 256 + threadIdx.x;        // 64*36*64
        int cop = idx & 63;
        int rest = idx >> 6;
        int ck = rest % 36, q = rest / 36;
        float w0 = wconv[(size_t)(2 * cop)     * 2304 + q * 36 + ck];
        float w1 = wconv[(size_t)(2 * cop + 1) * 2304 + q * 36 + ck];
        g_wtp[idx] = pk2(w0, w1);
        return;
    }
    blk -= NWT;
    {
        const float* w; ull* dst; int CIN; int t;
        if (blk < NWPL) { w = w_low;  dst = g_wplow;  CIN = 128; t = blk * 256 + threadIdx.x; }
        else            { w = w_high; dst = g_wphigh; CIN = 256; t = (blk - NWPL) * 256 + threadIdx.x; }
        int e = t % 288;
        int rest = t / 288;
        int NCH = CIN / 4;
        int chunk = rest % NCH, cg = rest / NCH;
        int cc = e / 72, rem = e % 72;
        int k = rem >> 3, j = rem & 7;
        int ci = chunk * 4 + cc;
        float w0 = w[((size_t)(cg * 16 + j) * CIN + ci) * 9 + k];
        float w1 = w[((size_t)(cg * 16 + j + 8) * CIN + ci) * 9 + k];
        dst[t] = pk2(w0, w1);
    }
}

// ---------------- 2) fused conv3x3 + BN + ReLU (unchanged, proven) -----------
#define PATCH_F   (4 * 34 * 40)
#define PATCH_B   (PATCH_F * 4)
#define WBUF_B    (288 * 8)
#define CONV_SMEM_BYTES (3 * (PATCH_B + WBUF_B))   // 72192
__global__ void __launch_bounds__(256, 2) conv_fused(
    const float* __restrict__ g_lo, const float* __restrict__ bb_lo,
    const float* __restrict__ mm_lo, const float* __restrict__ vv_lo,
    const float* __restrict__ g_hi, const float* __restrict__ bb_hi,
    const float* __restrict__ mm_hi, const float* __restrict__ vv_hi)
{
    extern __shared__ __align__(16) char dynsm[];
    float* patchS = (float*)dynsm;
    ull*   wS     = (ull*)(dynsm + 3 * PATCH_B);

    int bz = blockIdx.z;
    bool hi = bz >= 16;
    int bzl = hi ? bz - 16 : bz;
    int b   = bzl >> 3;
    int cg  = bzl & 7;
    int co0 = cg << 4;
    int x0 = blockIdx.x << 5, y0 = blockIdx.y << 5;
    int tx = threadIdx.x, ty = threadIdx.y;
    int tid = ty * 16 + tx;

    const int NCH = hi ? 64 : 32;
    const float* xp = hi ? g_xup_pad + (size_t)b * 256 * PADHW
                         : g_xlow_pad + (size_t)b * 128 * PADHW;
    const ull* wsrc = (hi ? g_wphigh : g_wplow) + (size_t)cg * NCH * 288;
    const float* gg  = hi ? g_hi  : g_lo;
    const float* bbp = hi ? bb_hi : bb_lo;
    const float* mmp = hi ? mm_hi : mm_lo;
    const float* vvp = hi ? vv_hi : vv_lo;
    int chan_base = hi ? 128 : 0;

    unsigned pS0 = smem_u32(patchS);
    unsigned wS0 = smem_u32(wS);

    auto issue = [&](int c, int buf) {
        const float* src_base = xp + (size_t)(c * 4) * PADHW;
        unsigned pdst = pS0 + buf * PATCH_B;
        for (int i = tid; i < 1360; i += 256) {
            int cc = i / 340;
            int r  = i - cc * 340;
            int row = r / 10, seg = r - row * 10;
            const float* src = src_base + (size_t)cc * PADHW
                             + (y0 + row) * PADW + x0 + seg * 4;
            cp16(pdst + (cc * 1360 + row * 40 + seg * 4) * 4, src);
        }
        if (tid < 144)
            cp16(wS0 + buf * WBUF_B + tid * 16, wsrc + (size_t)c * 288 + tid * 2);
        CP_COMMIT();
    };

    ull acc2[32];
#pragma unroll
    for (int i = 0; i < 32; i++) acc2[i] = 0ull;

    issue(0, 0);
    issue(1, 1);

    for (int c = 0; c < NCH; c++) {
        if (c + 1 < NCH) { CP_WAIT1(); } else { CP_WAIT0(); }
        __syncthreads();
        if (c + 2 < NCH) issue(c + 2, (c + 2) % 3);

        int buf = c % 3;
        const float* pd = patchS + buf * PATCH_F;
        const ull*   wp = wS + buf * 288;
#pragma unroll
        for (int cc = 0; cc < 4; cc++) {
            const float* pdc = pd + cc * 1360;
#pragma unroll
            for (int k = 0; k < 9; k++) {
                int dy = k / 3, dx = k % 3;
                float a0 = pdc[(ty + dy) * 40 + tx + dx + 3];
                float a1 = pdc[(ty + dy) * 40 + tx + 16 + dx + 3];
                float a2 = pdc[(ty + 16 + dy) * 40 + tx + dx + 3];
                float a3 = pdc[(ty + 16 + dy) * 40 + tx + 16 + dx + 3];
                ull p0 = pk2(a0, a0), p1 = pk2(a1, a1);
                ull p2 = pk2(a2, a2), p3 = pk2(a3, a3);
                const ull* wr = wp + (cc * 9 + k) * 8;
#pragma unroll
                for (int j = 0; j < 8; j++) {
                    ull wv = wr[j];
                    acc2[j * 4 + 0] = ffma2(wv, p0, acc2[j * 4 + 0]);
                    acc2[j * 4 + 1] = ffma2(wv, p1, acc2[j * 4 + 1]);
                    acc2[j * 4 + 2] = ffma2(wv, p2, acc2[j * 4 + 2]);
                    acc2[j * 4 + 3] = ffma2(wv, p3, acc2[j * 4 + 3]);
                }
            }
        }
        __syncthreads();
    }

    float sc[16], tc[16];
#pragma unroll
    for (int co = 0; co < 16; co++) {
        int c = co0 + co;
        sc[co] = gg[c] * rsqrtf(vvp[c] + 1e-5f);
        tc[co] = bbp[c] - mmp[c] * sc[co];
    }
#pragma unroll
    for (int q = 0; q < 4; q++) {
        int py = y0 + ty + ((q & 2) << 3);
        int px = x0 + tx + ((q & 1) << 4);
        float* dst = g_xmerge + ((size_t)b * HW + py * WW + px) * 256
                   + chan_base + co0;
        float v[16];
#pragma unroll
        for (int j = 0; j < 8; j++) {
            float lo, hi2;
            int qq = ((q & 2) ? 2 : 0) + (q & 1);
            upk2(acc2[j * 4 + qq], lo, hi2);
            v[j]     = fmaxf(lo  * sc[j]     + tc[j],     0.f);
            v[j + 8] = fmaxf(hi2 * sc[j + 8] + tc[j + 8], 0.f);
        }
#pragma unroll
        for (int c4 = 0; c4 < 4; c4++)
            ((float4*)dst)[c4] =
                make_float4(v[c4*4], v[c4*4+1], v[c4*4+2], v[c4*4+3]);
    }
}

// ---------------- 3) 1x1 convs: offset (18) + mask (9, sigmoid) --------------
__global__ void __launch_bounds__(256) offmask_kernel(
    const float* __restrict__ w_off, const float* __restrict__ b_off,
    const float* __restrict__ w_mask, const float* __restrict__ b_mask)
{
    __shared__ ull wpk[128 * 27];
    int tid = threadIdx.x;
    for (int i = tid; i < 128 * 27; i += 256) {
        int j = i / 27, o = i % 27;
        int c = 2 * j;
        float lo = (o < 18) ? w_off[o * 256 + c]     : w_mask[(o - 18) * 256 + c];
        float hi = (o < 18) ? w_off[o * 256 + c + 1] : w_mask[(o - 18) * 256 + c + 1];
        wpk[i] = pk2(lo, hi);
    }
    __syncthreads();

    int gpix = blockIdx.x * 256 + tid;
    int b = gpix >> 14, pix = gpix & 16383;
    const ull* xp = (const ull*)(g_xmerge + (size_t)gpix * 256);

    ull acc2[27];
#pragma unroll
    for (int o = 0; o < 27; o++) acc2[o] = 0ull;

#pragma unroll 8
    for (int j = 0; j < 128; j++) {
        ull xv = __ldg(xp + j);
#pragma unroll
        for (int o = 0; o < 27; o++)
            acc2[o] = ffma2(wpk[j * 27 + o], xv, acc2[o]);
    }

#pragma unroll
    for (int o = 0; o < 18; o++) {
        float lo, hi; upk2(acc2[o], lo, hi);
        g_offset[((size_t)b * 18 + o) * HW + pix] = lo + hi + b_off[o];
    }
#pragma unroll
    for (int o = 0; o < 9; o++) {
        float lo, hi; upk2(acc2[18 + o], lo, hi);
        float a = lo + hi + b_mask[o];
        g_mask[((size_t)b * 9 + o) * HW + pix] = 1.f / (1.f + __expf(-a));
    }
}

// ---------------- 4) deformable conv 3x3 + ReLU (v4.1) -----------------------
// v4 + 16B-aligned vals rows (pad 68) so GEMM reads vals as ONE LDS.128
// per (ck) instead of 4 LDS.32 (dominant L1 term -> /4).
// Dynamic smem (94464 B):
//   [0,     36864)  ull   wskB[2][36*64]   weight pairs, double-buffered
//   [36864, 76032)  float vals[9*16*68]    gathered vals [k][cc][p] pad68
//   [76032, 85248)  int   mI[4][576]
//   [85248, 94464)  float mW[4][576]
#define DEF_SMEM_BYTES 94464
__global__ void __launch_bounds__(256) deform_kernel(float* __restrict__ out)
{
    extern __shared__ __align__(16) char dyn[];
    ull*   wskB = (ull*)dyn;                    // [2][2304]
    float* vals = (float*)(dyn + 36864);        // [ (k*16+cc)*68 + p ]
    int*   mI0  = (int*)(dyn + 76032);
    int*   mI1  = mI0 + 576;
    int*   mI2  = mI1 + 576;
    int*   mI3  = mI2 + 576;
    float* mW0  = (float*)(dyn + 85248);
    float* mW1  = mW0 + 576;
    float* mW2  = mW1 + 576;
    float* mW3  = mW2 + 576;

    int b = blockIdx.z;
    int gx0 = blockIdx.x << 3, gy0 = blockIdx.y << 3;
    int tid = threadIdx.x;
    unsigned wskA = smem_u32(wskB);

    // weight copy for 4-channel chunk q into buffer buf (18432 B = 1152 cp16)
    auto issue_w = [&](int q, int buf) {
        const float4* src = (const float4*)(g_wtp + (size_t)q * 2304);
        unsigned dst = wskA + buf * 18432;
#pragma unroll
        for (int j = 0; j < 5; j++) {
            int i = tid + j * 256;
            if (i < 1152) cp16(dst + i * 16, src + i);
        }
        CP_COMMIT();
    };

    // per-(pixel,tap) meta
    for (int e = tid; e < 576; e += 256) {
        int p = e & 63, k = e >> 6;
        int gy = gy0 + (p >> 3), gx = gx0 + (p & 7);
        int pix = gy * WW + gx;
        float dy = g_offset[((size_t)b * 18 + 2 * k) * HW + pix];
        float dx = g_offset[((size_t)b * 18 + 2 * k + 1) * HW + pix];
        float mk = g_mask[((size_t)b * 9 + k) * HW + pix];
        float ys = (float)gy + (float)(k / 3 - 1) + dy;
        float xs = (float)gx + (float)(k % 3 - 1) + dx;
        float y0f = floorf(ys), x0f = floorf(xs);
        int y0 = (int)y0f, x0 = (int)x0f;
        float wy = ys - y0f, wx = xs - x0f;
        bool vy0 = (y0 >= 0) && (y0 < HH);
        bool vy1 = (y0 + 1 >= 0) && (y0 + 1 < HH);
        bool vx0 = (x0 >= 0) && (x0 < WW);
        bool vx1 = (x0 + 1 >= 0) && (x0 + 1 < WW);
        int y0c = min(max(y0, 0), HH - 1), y1c = min(max(y0 + 1, 0), HH - 1);
        int x0c = min(max(x0, 0), WW - 1), x1c = min(max(x0 + 1, 0), WW - 1);
        mI0[e] = (y0c * WW + x0c) * 256;  mW0[e] = (vy0 && vx0) ? (1.f - wy) * (1.f - wx) * mk : 0.f;
        mI1[e] = (y0c * WW + x1c) * 256;  mW1[e] = (vy0 && vx1) ? (1.f - wy) * wx * mk : 0.f;
        mI2[e] = (y1c * WW + x0c) * 256;  mW2[e] = (vy1 && vx0) ? wy * (1.f - wx) * mk : 0.f;
        mI3[e] = (y1c * WW + x1c) * 256;  mW3[e] = (vy1 && vx1) ? wy * wx * mk : 0.f;
    }

    issue_w(0, 0);        // weights(0) fly under meta + first gather

    ull acc2[16];         // [r (4 px)][j (4 co-pairs)]
#pragma unroll
    for (int i = 0; i < 16; i++) acc2[i] = 0ull;

    const float* xb = g_xmerge + (size_t)b * HW * 256;
    int ppg  = tid & 15;          // pixels ppg*4 .. ppg*4+3
    int cog  = tid >> 4;          // co-pairs cog*4..+3 (cos cog*8..cog*8+7)
    int wid  = tid >> 5;          // gather warp id
    int lane = tid & 31;
    int half = lane >> 4;         // entry selector within pair
    int cch  = lane & 15;         // channel within group

    for (int g = 0; g < 16; g++) {
        __syncthreads();          // vals free (prev group GEMM done) / meta ready
        // ---- gather 16 channels (c0g..c0g+15) for all 576 (px,tap) ---------
        int c0g = g * 16;
        const float* xc = xb + c0g + cch;
        for (int it = 0; it < 36; it++) {
            int e = wid * 72 + it * 2 + half;
            int i0 = mI0[e], i1 = mI1[e], i2 = mI2[e], i3 = mI3[e];
            float w0 = mW0[e], w1 = mW1[e], w2 = mW2[e], w3 = mW3[e];
            float v = w0 * __ldg(xc + i0) + w1 * __ldg(xc + i1)
                    + w2 * __ldg(xc + i2) + w3 * __ldg(xc + i3);
            int k = e >> 6, p = e & 63;
            vals[(k * 16 + cch) * 68 + p] = v;
        }
        // ---- 4 GEMM sub-chunks of 4 channels -------------------------------
        for (int s = 0; s < 4; s++) {
            int q = g * 4 + s;
            CP_WAIT0();           // weights(q) landed
            __syncthreads();      // weights + (s==0) vals visible to all
            if (q + 1 < 64) issue_w(q + 1, (q + 1) & 1);

            const ull* wsk = wskB + (q & 1) * 2304;
#pragma unroll
            for (int cc4 = 0; cc4 < 4; cc4++) {
#pragma unroll
                for (int k = 0; k < 9; k++) {
                    const ull* wr = wsk + (cc4 * 9 + k) * 64 + cog * 4;
                    ull w0 = wr[0], w1 = wr[1], w2 = wr[2], w3 = wr[3];
                    float4 v4 = *(const float4*)
                        &vals[(k * 16 + s * 4 + cc4) * 68 + ppg * 4];
                    ull da = pk2(v4.x, v4.x);
                    ull db = pk2(v4.y, v4.y);
                    ull dc = pk2(v4.z, v4.z);
                    ull dd = pk2(v4.w, v4.w);
                    acc2[0]  = ffma2(w0, da, acc2[0]);
                    acc2[1]  = ffma2(w1, da, acc2[1]);
                    acc2[2]  = ffma2(w2, da, acc2[2]);
                    acc2[3]  = ffma2(w3, da, acc2[3]);
                    acc2[4]  = ffma2(w0, db, acc2[4]);
                    acc2[5]  = ffma2(w1, db, acc2[5]);
                    acc2[6]  = ffma2(w2, db, acc2[6]);
                    acc2[7]  = ffma2(w3, db, acc2[7]);
                    acc2[8]  = ffma2(w0, dc, acc2[8]);
                    acc2[9]  = ffma2(w1, dc, acc2[9]);
                    acc2[10] = ffma2(w2, dc, acc2[10]);
                    acc2[11] = ffma2(w3, dc, acc2[11]);
                    acc2[12] = ffma2(w0, dd, acc2[12]);
                    acc2[13] = ffma2(w1, dd, acc2[13]);
                    acc2[14] = ffma2(w2, dd, acc2[14]);
                    acc2[15] = ffma2(w3, dd, acc2[15]);
                }
            }
            __syncthreads();      // GEMM done before weights buf reuse / vals regather
        }
    }

    // epilogue: ReLU + NCHW store (co pairs per pixel)
#pragma unroll
    for (int r = 0; r < 4; r++) {
        int p = ppg * 4 + r;
        int gy = gy0 + (p >> 3), gx = gx0 + (p & 7);
        int pix = gy * WW + gx;
#pragma unroll
        for (int j = 0; j < 4; j++) {
            float a0, a1; upk2(acc2[r * 4 + j], a0, a1);
            int co = cog * 8 + 2 * j;
            out[((size_t)b * 128 + co) * HW + pix]     = fmaxf(a0, 0.f);
            out[((size_t)b * 128 + co + 1) * HW + pix] = fmaxf(a1, 0.f);
        }
    }
}

// ---------------- launch -----------------------------------------------------
extern "C" void kernel_launch(void* const* d_in, const int* in_sizes, int n_in,
                              void* d_out, int out_size) {
    const float* x_low  = (const float*)d_in[0];
    const float* x_high = (const float*)d_in[1];
    const float* w_low  = (const float*)d_in[2];
    const float* g_low  = (const float*)d_in[3];
    const float* b_low  = (const float*)d_in[4];
    const float* m_low  = (const float*)d_in[5];
    const float* v_low  = (const float*)d_in[6];
    const float* w_high = (const float*)d_in[7];
    const float* g_high = (const float*)d_in[8];
    const float* b_high = (const float*)d_in[9];
    const float* m_high = (const float*)d_in[10];
    const float* v_high = (const float*)d_in[11];
    const float* w_off  = (const float*)d_in[12];
    const float* b_off  = (const float*)d_in[13];
    const float* w_mask = (const float*)d_in[14];
    const float* b_mask = (const float*)d_in[15];
    const float* w_conv = (const float*)d_in[16];
    float* out = (float*)d_out;

    cudaFuncSetAttribute(deform_kernel,
                         cudaFuncAttributeMaxDynamicSharedMemorySize,
                         DEF_SMEM_BYTES);
    cudaFuncSetAttribute(conv_fused,
                         cudaFuncAttributeMaxDynamicSharedMemorySize,
                         CONV_SMEM_BYTES);

    prep_kernel<<<NPREP, 256>>>(x_low, x_high, w_low, w_high, w_conv);

    conv_fused<<<dim3(4, 4, 32), dim3(16, 16), CONV_SMEM_BYTES>>>(
        g_low, b_low, m_low, v_low, g_high, b_high, m_high, v_high);

    offmask_kernel<<<128, 256>>>(w_off, b_off, w_mask, b_mask);

    deform_kernel<<<dim3(16, 16, NB), 256, DEF_SMEM_BYTES>>>(out);
}